// round 14
// baseline (speedup 1.0000x reference)
#include <cuda_runtime.h>
#include <cuda_bf16.h>
#include <math.h>

#define PI_F 3.14159265358979323846f
#define Bb   2
#define Cc   128
#define Hh   128
#define Ww   256
#define HW   32768
#define AUXC 133
#define KWF  129
#define ASTR 88

__device__ float2 g_R[Bb*KWF*Cc*Hh];
__device__ float  g_part[Bb*KWF*64*128];
__device__ float  g_feh[Bb*Hh*KWF];
__device__ float  g_fe[Bb*HW];
__device__ float  g_off[Bb*18*HW];
__device__ float  g_gbuf[Bb*66*HW];
__device__ float  g_ybase[Bb*Cc*HW];
__device__ float  g_xT[Bb*HW*Cc];
__device__ float  g_bF[96];
__device__ __align__(16) __nv_bfloat16 g_xbh[(size_t)Bb*HW*Cc];
__device__ __align__(16) __nv_bfloat16 g_xbl[(size_t)Bb*HW*Cc];
__device__ __align__(16) __nv_bfloat16 g_ath[(size_t)Bb*HW*16];
__device__ __align__(16) __nv_bfloat16 g_atl[(size_t)Bb*HW*16];
__device__ __align__(16) __nv_bfloat16 g_WBh[18*8192];
__device__ __align__(16) __nv_bfloat16 g_WBl[18*8192];
__device__ __align__(16) __nv_bfloat16 g_WDh[18*8192];
__device__ __align__(16) __nv_bfloat16 g_WDl[18*8192];
__device__ __align__(16) __nv_bfloat16 g_WAh[27*8192];
__device__ __align__(16) __nv_bfloat16 g_WAl[27*8192];

__device__ __forceinline__ unsigned smem_u32(const void* p){
    unsigned r;
    asm("{.reg .u64 t; cvta.to.shared.u64 t, %1; cvt.u32.u64 %0, t;}" : "=r"(r) : "l"(p));
    return r;
}
__device__ __forceinline__ void ldsm4(unsigned* r, unsigned a){
    asm volatile("ldmatrix.sync.aligned.m8n8.x4.shared.b16 {%0,%1,%2,%3}, [%4];"
        : "=r"(r[0]),"=r"(r[1]),"=r"(r[2]),"=r"(r[3]) : "r"(a));
}
__device__ __forceinline__ void mma16816(float* d, const unsigned* a, unsigned b0, unsigned b1){
    asm volatile("mma.sync.aligned.m16n8k16.row.col.f32.bf16.bf16.f32 "
        "{%0,%1,%2,%3}, {%4,%5,%6,%7}, {%8,%9}, {%0,%1,%2,%3};"
        : "+f"(d[0]),"+f"(d[1]),"+f"(d[2]),"+f"(d[3])
        : "r"(a[0]),"r"(a[1]),"r"(a[2]),"r"(a[3]), "r"(b0),"r"(b1));
}
__device__ __forceinline__ void bsplit2(float v, __nv_bfloat16& h, __nv_bfloat16& l){
    h = __float2bfloat16(v);
    l = __float2bfloat16(v - __bfloat162float(h));
}

// ---------------- FFT over W: 4 rows per 512-thread CTA ------------------
__global__ void __launch_bounds__(512) fft_rows_k(const float* __restrict__ x) {
    __shared__ float2 sm[4][256];
    __shared__ float2 tw[128];
    int tid = threadIdx.x;
    int f = tid >> 7, t = tid & 127;
    int r = blockIdx.x*4 + f;
    int m = r & (Hh-1), c = (r >> 7) & (Cc-1), b = r >> 14;
    if (tid < 128) {
        float ang = -2.0f*PI_F*(float)tid/256.0f;
        tw[tid] = make_float2(cosf(ang), sinf(ang));
    }
    const float* row = x + ((size_t)(b*Cc + c)*Hh + m)*Ww;
    for (int i = t; i < 256; i += 128)
        sm[f][__brev(i) >> 24] = make_float2(row[i], 0.0f);
    __syncthreads();
#pragma unroll
    for (int s = 1; s <= 8; s++) {
        int half = 1 << (s-1);
        int pos = t & (half-1);
        int i0 = ((t >> (s-1)) << s) | pos, i1 = i0 + half;
        float2 w = tw[pos << (8-s)];
        float2 a = sm[f][i0], bv = sm[f][i1];
        float2 tt = make_float2(bv.x*w.x - bv.y*w.y, bv.x*w.y + bv.y*w.x);
        sm[f][i0] = make_float2(a.x + tt.x, a.y + tt.y);
        sm[f][i1] = make_float2(a.x - tt.x, a.y - tt.y);
        __syncthreads();
    }
    g_R[((size_t)(b*KWF + t)*Cc + c)*Hh + m] = sm[f][t];
    if (t == 0)
        g_R[((size_t)(b*KWF + 128)*Cc + c)*Hh + m] = sm[f][128];
}

// ---------------- FFT over H: 4 channel-pairs per 512-thread CTA ---------
__global__ void __launch_bounds__(512) fft_cols_k(void) {
    __shared__ float2 sm[8][128];
    __shared__ float2 tw[64];
    __shared__ float  mg[4][128];
    int bid = blockIdx.x;
    int t16 = bid & 15;
    int kw = (bid >> 4) % KWF;
    int b  = bid / (16*KWF);
    int tid = threadIdx.x;
    int ch = tid >> 6, lane = tid & 63;
    int cp = t16*4 + (ch >> 1);
    int c  = cp*2 + (ch & 1);
    if (tid < 64) {
        float ang = -2.0f*PI_F*(float)tid/128.0f;
        tw[tid] = make_float2(cosf(ang), sinf(ang));
    }
    const float2* base = g_R + (size_t)(b*KWF + kw)*Cc*Hh + c*Hh;
#pragma unroll
    for (int i = lane; i < 128; i += 64)
        sm[ch][__brev(i) >> 25] = base[i];
    __syncthreads();
#pragma unroll
    for (int s = 1; s <= 7; s++) {
        int half = 1 << (s-1);
        int pos = lane & (half-1);
        int i0 = ((lane >> (s-1)) << s) | pos, i1 = i0 + half;
        float2 w = tw[pos << (7-s)];
        float2 a = sm[ch][i0], bv = sm[ch][i1];
        float2 t = make_float2(bv.x*w.x - bv.y*w.y, bv.x*w.y + bv.y*w.x);
        sm[ch][i0] = make_float2(a.x + t.x, a.y + t.y);
        sm[ch][i1] = make_float2(a.x - t.x, a.y - t.y);
        __syncthreads();
    }
    if ((ch & 1) == 0)
        for (int i = lane; i < 128; i += 64) {
            float2 X = sm[ch][i];
            mg[ch >> 1][i] = sqrtf(X.x*X.x + X.y*X.y);
        }
    __syncthreads();
    if ((ch & 1) == 1)
        for (int i = lane; i < 128; i += 64) {
            float2 X = sm[ch][i];
            g_part[((size_t)(b*KWF + kw)*64 + cp)*128 + i] =
                mg[ch >> 1][i] + sqrtf(X.x*X.x + X.y*X.y);
        }
}

__global__ void reduce_feh_k(void) {
    int bid = blockIdx.x;
    int kw = bid % KWF, b = bid / KWF;
    int kh = threadIdx.x;
    float s = 0.0f;
    const float* p = g_part + (size_t)bid*64*128 + kh;
#pragma unroll 8
    for (int cp = 0; cp < 64; cp++) s += p[cp*128];
    g_feh[(size_t)(b*Hh + kh)*KWF + kw] = s * (1.0f/(128.0f*sqrtf((float)HW)));
}

__global__ void resize_fe_k(void) {
    int idx = blockIdx.x*blockDim.x + threadIdx.x;
    if (idx >= Bb*HW) return;
    int w = idx & (Ww-1), h = (idx >> 8) & (Hh-1), b = idx >> 15;
    float px = ((float)w + 0.5f)*(129.0f/256.0f) - 0.5f;
    float x0f = floorf(px);
    float f = px - x0f;
    int x0 = min(max((int)x0f, 0), 128), x1 = min(max((int)x0f + 1, 0), 128);
    const float* r = g_feh + (size_t)(b*Hh + h)*KWF;
    g_fe[idx] = r[x0]*(1.0f-f) + r[x1]*f;
}

// ---------------- aux tail: 16 NHWC channels (coords, fe, pad) -----------
__global__ void auxtail_k(void) {
    int idx = blockIdx.x*blockDim.x + threadIdx.x;
    if (idx >= Bb*HW) return;
    int w = idx & (Ww-1), h = (idx >> 8) & (Hh-1);
    float th = -PI_F + (2.0f*PI_F/255.0f)*(float)w;
    float ph = -0.5f*PI_F + (PI_F/127.0f)*(float)h;
    float v[16] = {sinf(th), cosf(th), sinf(ph), cosf(ph), g_fe[idx],
                   0,0,0,0,0,0,0,0,0,0,0};
    __nv_bfloat16* oh = g_ath + (size_t)idx*16;
    __nv_bfloat16* ol = g_atl + (size_t)idx*16;
#pragma unroll
    for (int k = 0; k < 16; k++) {
        __nv_bfloat16 hb, lb; bsplit2(v[k], hb, lb);
        oh[k] = hb; ol[k] = lb;
    }
}

// ---------------- transpose + bf16 hi/lo split ---------------------------
__global__ void transpose_k(const float* __restrict__ x) {
    __shared__ float t[32][33];
    int b = blockIdx.z, p0 = blockIdx.x*32, c0 = blockIdx.y*32;
    int tx = threadIdx.x, ty = threadIdx.y;
#pragma unroll
    for (int j = 0; j < 4; j++)
        t[ty + j*8][tx] = x[(size_t)(b*Cc + c0 + ty + j*8)*HW + p0 + tx];
    __syncthreads();
#pragma unroll
    for (int j = 0; j < 4; j++) {
        float v = t[tx][ty + j*8];
        size_t o = (size_t)(b*HW + p0 + ty + j*8)*Cc + c0 + tx;
        g_xT[o] = v;
        __nv_bfloat16 hb, lb; bsplit2(v, hb, lb);
        g_xbh[o] = hb; g_xbl[o] = lb;
    }
}

// ---------------- weight preps -------------------------------------------
__global__ void wprep_k(const float* __restrict__ bw) {
    int idx = blockIdx.x*blockDim.x + threadIdx.x;
    if (idx >= 18*8192) return;
    int c = idx >> 13, r = idx & 8191;
    int co = r >> 6, k = r & 63;
    int kk = c >> 1, ci = (c & 1)*64 + k;
    float v = bw[(size_t)(co*Cc + ci)*9 + kk];
    __nv_bfloat16 hb, lb; bsplit2(v, hb, lb);
    g_WBh[idx] = hb; g_WBl[idx] = lb;
}
__global__ void wprepD_k(const float* __restrict__ dw) {
    int idx = blockIdx.x*blockDim.x + threadIdx.x;
    if (idx >= 18*8192) return;
    int c = idx >> 13, r = idx & 8191;
    int co = r >> 6, k = r & 63;
    int kk = c >> 1, ci = (c & 1)*64 + k;
    float v = dw[(size_t)(co*Cc + ci)*9 + kk];
    __nv_bfloat16 hb, lb; bsplit2(v, hb, lb);
    g_WDh[idx] = hb; g_WDl[idx] = lb;
}
__global__ void wprepA_k(const float* __restrict__ ow, const float* __restrict__ ob,
                         const float* __restrict__ gw, const float* __restrict__ gb) {
    int idx = blockIdx.x*blockDim.x + threadIdx.x;
    if (idx < 96) g_bF[idx] = (idx < 18) ? ob[idx] : (idx < 84 ? gb[idx-18] : 0.0f);
    if (idx >= 27*8192) return;
    int c = idx >> 13, r = idx & 8191;
    int co = r >> 6, k = r & 63;
    int tap = c / 3, sub = c % 3;
    int ci = sub*64 + k;
    float v = 0.0f;
    if (co < 84 && ci < AUXC)
        v = (co < 18) ? ow[(size_t)(co*AUXC + ci)*9 + tap]
                      : gw[(size_t)((co-18)*AUXC + ci)*9 + tap];
    __nv_bfloat16 hb, lb; bsplit2(v, hb, lb);
    g_WAh[idx] = hb; g_WAl[idx] = lb;
}

// ---------------- mma.sync base conv -------------------------------------
__global__ void __launch_bounds__(256) conv_mma(const float* __restrict__ bias) {
    extern __shared__ __align__(16) unsigned char dsm[];
    __nv_bfloat16* Ah = (__nv_bfloat16*)dsm;
    __nv_bfloat16* Al = Ah + 128*ASTR;
    __nv_bfloat16* Bh = Al + 128*ASTR;
    __nv_bfloat16* Bl = Bh + 128*ASTR;
    int tid = threadIdx.x;
    int wid = tid >> 5, lane = tid & 31;
    int co0 = (wid & 1)*64, pxo = (wid >> 1)*32;
    int blk = blockIdx.x;
    int b = blk >> 8;
    int px0 = (blk & 255) * 128;
    int h = px0 >> 8, w0 = px0 & 255;
    int r15 = lane & 15, r16 = (lane >> 4)*8;

    float acc[4][4][4];
#pragma unroll
    for (int mf = 0; mf < 4; mf++)
#pragma unroll
        for (int nf = 0; nf < 4; nf++)
#pragma unroll
            for (int q = 0; q < 4; q++) acc[mf][nf][q] = 0.0f;

    for (int c = 0; c < 18; c++) {
        int kk = c >> 1;
        int dy = kk/3 - 1, dx = kk%3 - 1;
        int ci0 = (c & 1)*64;
        __syncthreads();
        for (int i = tid; i < 2048; i += 256) {
            int buf = i >> 10, idx = i & 1023;
            int row = idx >> 3, seg = idx & 7;
            *((float4*)((buf ? Al : Ah) + row*ASTR) + seg) =
                *((const float4*)((buf ? g_WBl : g_WBh) + (size_t)c*8192 + row*64) + seg);
        }
        int sh = h + dy;
        for (int i = tid; i < 2048; i += 256) {
            int buf = i >> 10, idx = i & 1023;
            int p = idx >> 3, seg = idx & 7;
            int sw = w0 + p + dx;
            float4 v = make_float4(0.f,0.f,0.f,0.f);
            if (sw >= 0 && sw < Ww && sh >= 0 && sh < Hh)
                v = *((const float4*)((buf ? g_xbl : g_xbh) +
                      ((size_t)(b*HW) + sh*Ww + sw)*Cc + ci0) + seg);
            *((float4*)((buf ? Bl : Bh) + p*ASTR) + seg) = v;
        }
        __syncthreads();
#pragma unroll
        for (int ks = 0; ks < 4; ks++) {
            unsigned bh[2][4], bl[2][4];
#pragma unroll
            for (int nh = 0; nh < 2; nh++) {
                ldsm4(bh[nh], smem_u32(Bh + (pxo + nh*16 + r15)*ASTR + ks*16 + r16));
                ldsm4(bl[nh], smem_u32(Bl + (pxo + nh*16 + r15)*ASTR + ks*16 + r16));
            }
#pragma unroll
            for (int mf = 0; mf < 4; mf++) {
                unsigned ah[4], al[4];
                ldsm4(ah, smem_u32(Ah + (co0 + mf*16 + r15)*ASTR + ks*16 + r16));
                ldsm4(al, smem_u32(Al + (co0 + mf*16 + r15)*ASTR + ks*16 + r16));
#pragma unroll
                for (int nf = 0; nf < 4; nf++) {
                    int nh = nf >> 1, sel = nf & 1;
                    mma16816(acc[mf][nf], ah, bh[nh][sel], bh[nh][sel+2]);
                    mma16816(acc[mf][nf], ah, bl[nh][sel], bl[nh][sel+2]);
                    mma16816(acc[mf][nf], al, bh[nh][sel], bh[nh][sel+2]);
                }
            }
        }
    }
    int gid = lane >> 2, t4 = lane & 3;
#pragma unroll
    for (int mf = 0; mf < 4; mf++) {
#pragma unroll
        for (int nf = 0; nf < 4; nf++) {
            int co = co0 + mf*16 + gid;
            int px = px0 + pxo + nf*8 + t4*2;
            float* d = acc[mf][nf];
            *(float2*)(g_ybase + (size_t)(b*Cc + co  )*HW + px) =
                make_float2(d[0] + bias[co],   d[1] + bias[co]);
            *(float2*)(g_ybase + (size_t)(b*Cc + co+8)*HW + px) =
                make_float2(d[2] + bias[co+8], d[3] + bias[co+8]);
        }
    }
}

// ---------------- mma.sync aux conv (offset+gate) ------------------------
__global__ void __launch_bounds__(256) conv_aux_mma(void) {
    extern __shared__ __align__(16) unsigned char dsm[];
    __nv_bfloat16* Ah = (__nv_bfloat16*)dsm;
    __nv_bfloat16* Al = Ah + 128*ASTR;
    __nv_bfloat16* Bh = Al + 128*ASTR;
    __nv_bfloat16* Bl = Bh + 128*ASTR;
    int tid = threadIdx.x;
    int wid = tid >> 5, lane = tid & 31;
    int co0 = (wid & 1)*64, pxo = (wid >> 1)*32;
    int blk = blockIdx.x;
    int b = blk >> 8;
    int px0 = (blk & 255) * 128;
    int h = px0 >> 8, w0 = px0 & 255;
    int r15 = lane & 15, r16 = (lane >> 4)*8;

    float acc[4][4][4];
#pragma unroll
    for (int mf = 0; mf < 4; mf++)
#pragma unroll
        for (int nf = 0; nf < 4; nf++)
#pragma unroll
            for (int q = 0; q < 4; q++) acc[mf][nf][q] = 0.0f;

    for (int c = 0; c < 27; c++) {
        int tap = c / 3, sub = c - tap*3;
        int dy = tap/3 - 1, dx = tap%3 - 1;
        __syncthreads();
        for (int i = tid; i < 2048; i += 256) {
            int buf = i >> 10, idx = i & 1023;
            int row = idx >> 3, seg = idx & 7;
            *((float4*)((buf ? Al : Ah) + row*ASTR) + seg) =
                *((const float4*)((buf ? g_WAl : g_WAh) + (size_t)c*8192 + row*64) + seg);
        }
        int sh = h + dy;
        if (sub < 2) {
            int ci0 = sub*64;
            for (int i = tid; i < 2048; i += 256) {
                int buf = i >> 10, idx = i & 1023;
                int p = idx >> 3, seg = idx & 7;
                int sw = w0 + p + dx;
                float4 v = make_float4(0.f,0.f,0.f,0.f);
                if (sw >= 0 && sw < Ww && sh >= 0 && sh < Hh)
                    v = *((const float4*)((buf ? g_xbl : g_xbh) +
                          ((size_t)(b*HW) + sh*Ww + sw)*Cc + ci0) + seg);
                *((float4*)((buf ? Bl : Bh) + p*ASTR) + seg) = v;
            }
        } else {
            for (int i = tid; i < 512; i += 256) {
                int buf = i >> 8, idx = i & 255;
                int p = idx >> 1, seg = idx & 1;
                int sw = w0 + p + dx;
                float4 v = make_float4(0.f,0.f,0.f,0.f);
                if (sw >= 0 && sw < Ww && sh >= 0 && sh < Hh)
                    v = *((const float4*)((buf ? g_atl : g_ath) +
                          ((size_t)(b*HW) + sh*Ww + sw)*16) + seg);
                *((float4*)((buf ? Bl : Bh) + p*ASTR) + seg) = v;
            }
        }
        __syncthreads();
        int nks = (sub < 2) ? 4 : 1;
        for (int ks = 0; ks < nks; ks++) {
            unsigned bh[2][4], bl[2][4];
#pragma unroll
            for (int nh = 0; nh < 2; nh++) {
                ldsm4(bh[nh], smem_u32(Bh + (pxo + nh*16 + r15)*ASTR + ks*16 + r16));
                ldsm4(bl[nh], smem_u32(Bl + (pxo + nh*16 + r15)*ASTR + ks*16 + r16));
            }
#pragma unroll
            for (int mf = 0; mf < 4; mf++) {
                unsigned ah[4], al[4];
                ldsm4(ah, smem_u32(Ah + (co0 + mf*16 + r15)*ASTR + ks*16 + r16));
                ldsm4(al, smem_u32(Al + (co0 + mf*16 + r15)*ASTR + ks*16 + r16));
#pragma unroll
                for (int nf = 0; nf < 4; nf++) {
                    int nh = nf >> 1, sel = nf & 1;
                    mma16816(acc[mf][nf], ah, bh[nh][sel], bh[nh][sel+2]);
                    mma16816(acc[mf][nf], ah, bl[nh][sel], bl[nh][sel+2]);
                    mma16816(acc[mf][nf], al, bh[nh][sel], bh[nh][sel+2]);
                }
            }
        }
    }
    int gid = lane >> 2, t4 = lane & 3;
#pragma unroll
    for (int mf = 0; mf < 4; mf++) {
#pragma unroll
        for (int nf = 0; nf < 4; nf++) {
            int px = px0 + pxo + nf*8 + t4*2;
            float* d = acc[mf][nf];
#pragma unroll
            for (int half = 0; half < 2; half++) {
                int co = co0 + mf*16 + gid + half*8;
                float v0 = d[half*2] + g_bF[co], v1 = d[half*2+1] + g_bF[co];
                if (co < 18) {
                    *(float2*)(g_off + (size_t)(b*18 + co)*HW + px) = make_float2(v0, v1);
                } else if (co < 84) {
                    *(float2*)(g_gbuf + (size_t)(b*66 + co - 18)*HW + px) =
                        make_float2(fmaxf(v0, 0.0f), fmaxf(v1, 0.0f));
                }
            }
        }
    }
}

// ---------------- mma.sync deform GEMM + fused gate + blend --------------
__global__ void __launch_bounds__(256) deform_mma(
        const float* __restrict__ defb, const float* __restrict__ gw2,
        const float* __restrict__ gb2, float* __restrict__ out) {
    extern __shared__ __align__(16) unsigned char dsm[];
    __nv_bfloat16* Ah = (__nv_bfloat16*)dsm;
    __nv_bfloat16* Al = Ah + 128*ASTR;
    __nv_bfloat16* Bh = Al + 128*ASTR;
    __nv_bfloat16* Bl = Bh + 128*ASTR;
    __shared__ int   sC[4][128];
    __shared__ float sWt[4][128];
    __shared__ float sGate[128];
    int tid = threadIdx.x;
    int wid = tid >> 5, lane = tid & 31;
    int co0 = (wid & 1)*64, pxo = (wid >> 1)*32;
    int blk = blockIdx.x;
    int b = blk >> 8;
    int px0 = (blk & 255) * 128;
    int r15 = lane & 15, r16 = (lane >> 4)*8;

    // fused gate: sigmoid(gw2 . gbuf + gb2) for this CTA's 128 pixels
    if (tid < 128) {
        int pp = px0 + tid;
        float s = gb2[0];
#pragma unroll 6
        for (int c = 0; c < 66; c++)
            s = fmaf(g_gbuf[(size_t)(b*66 + c)*HW + pp], gw2[c], s);
        sGate[tid] = 1.0f / (1.0f + __expf(-s));
    }

    float acc[4][4][4];
#pragma unroll
    for (int mf = 0; mf < 4; mf++)
#pragma unroll
        for (int nf = 0; nf < 4; nf++)
#pragma unroll
            for (int q = 0; q < 4; q++) acc[mf][nf][q] = 0.0f;

    for (int c = 0; c < 18; c++) {
        int kk = c >> 1;
        int ci0 = (c & 1)*64;
        __syncthreads();
        if ((c & 1) == 0 && tid < 128) {
            int pp = px0 + tid;
            int hh = pp >> 8, ww = pp & (Ww-1);
            float fpx = (float)ww + g_off[(size_t)(b*18 + 2*kk    )*HW + pp];
            float fpy = (float)hh + g_off[(size_t)(b*18 + 2*kk + 1)*HW + pp];
            float fx0 = floorf(fpx), fy0 = floorf(fpy);
            int X0 = (int)fx0, Y0 = (int)fy0;
            float fx = fpx - fx0, fy = fpy - fy0;
            float w00 = (1.0f-fx)*(1.0f-fy), w10 = fx*(1.0f-fy);
            float w01 = (1.0f-fx)*fy,        w11 = fx*fy;
            if (X0   < 0 || X0   >= Ww) { w00 = 0.0f; w01 = 0.0f; }
            if (X0+1 < 0 || X0+1 >= Ww) { w10 = 0.0f; w11 = 0.0f; }
            if (Y0   < 0 || Y0   >= Hh) { w00 = 0.0f; w10 = 0.0f; }
            if (Y0+1 < 0 || Y0+1 >= Hh) { w01 = 0.0f; w11 = 0.0f; }
            sC[0][tid] = min(max(X0,   0), Ww-1);
            sC[1][tid] = min(max(X0+1, 0), Ww-1);
            sC[2][tid] = min(max(Y0,   0), Hh-1);
            sC[3][tid] = min(max(Y0+1, 0), Hh-1);
            sWt[0][tid] = w00; sWt[1][tid] = w10; sWt[2][tid] = w01; sWt[3][tid] = w11;
        }
        __syncthreads();
        for (int i = tid; i < 2048; i += 256) {
            int buf = i >> 10, idx = i & 1023;
            int row = idx >> 3, seg = idx & 7;
            *((float4*)((buf ? Al : Ah) + row*ASTR) + seg) =
                *((const float4*)((buf ? g_WDl : g_WDh) + (size_t)c*8192 + row*64) + seg);
        }
        for (int i = tid; i < 2048; i += 256) {
            int p = i >> 4, g = i & 15;
            int cx0 = sC[0][p], cx1 = sC[1][p], cy0 = sC[2][p], cy1 = sC[3][p];
            float w00 = sWt[0][p], w10 = sWt[1][p], w01 = sWt[2][p], w11 = sWt[3][p];
            size_t base = (size_t)(b*HW)*Cc + (size_t)(ci0 + g*4);
            float4 a00 = *(const float4*)(g_xT + base + (size_t)(cy0*Ww + cx0)*Cc);
            float4 a10 = *(const float4*)(g_xT + base + (size_t)(cy0*Ww + cx1)*Cc);
            float4 a01 = *(const float4*)(g_xT + base + (size_t)(cy1*Ww + cx0)*Cc);
            float4 a11 = *(const float4*)(g_xT + base + (size_t)(cy1*Ww + cx1)*Cc);
            float4 r;
            r.x = w00*a00.x + w10*a10.x + w01*a01.x + w11*a11.x;
            r.y = w00*a00.y + w10*a10.y + w01*a01.y + w11*a11.y;
            r.z = w00*a00.z + w10*a10.z + w01*a01.z + w11*a11.z;
            r.w = w00*a00.w + w10*a10.w + w01*a01.w + w11*a11.w;
            __nv_bfloat16 h0, l0, h1, l1, h2, l2, h3, l3;
            bsplit2(r.x, h0, l0); bsplit2(r.y, h1, l1);
            bsplit2(r.z, h2, l2); bsplit2(r.w, h3, l3);
            __nv_bfloat162* dh = (__nv_bfloat162*)(Bh + p*ASTR + g*4);
            dh[0] = __nv_bfloat162(h0, h1); dh[1] = __nv_bfloat162(h2, h3);
            __nv_bfloat162* dl = (__nv_bfloat162*)(Bl + p*ASTR + g*4);
            dl[0] = __nv_bfloat162(l0, l1); dl[1] = __nv_bfloat162(l2, l3);
        }
        __syncthreads();
#pragma unroll
        for (int ks = 0; ks < 4; ks++) {
            unsigned bh[2][4], bl[2][4];
#pragma unroll
            for (int nh = 0; nh < 2; nh++) {
                ldsm4(bh[nh], smem_u32(Bh + (pxo + nh*16 + r15)*ASTR + ks*16 + r16));
                ldsm4(bl[nh], smem_u32(Bl + (pxo + nh*16 + r15)*ASTR + ks*16 + r16));
            }
#pragma unroll
            for (int mf = 0; mf < 4; mf++) {
                unsigned ah[4], al[4];
                ldsm4(ah, smem_u32(Ah + (co0 + mf*16 + r15)*ASTR + ks*16 + r16));
                ldsm4(al, smem_u32(Al + (co0 + mf*16 + r15)*ASTR + ks*16 + r16));
#pragma unroll
                for (int nf = 0; nf < 4; nf++) {
                    int nh = nf >> 1, sel = nf & 1;
                    mma16816(acc[mf][nf], ah, bh[nh][sel], bh[nh][sel+2]);
                    mma16816(acc[mf][nf], ah, bl[nh][sel], bl[nh][sel+2]);
                    mma16816(acc[mf][nf], al, bh[nh][sel], bh[nh][sel+2]);
                }
            }
        }
    }
    int gid = lane >> 2, t4 = lane & 3;
#pragma unroll
    for (int mf = 0; mf < 4; mf++) {
#pragma unroll
        for (int nf = 0; nf < 4; nf++) {
            int co = co0 + mf*16 + gid;
            int pxl = pxo + nf*8 + t4*2;
            int px = px0 + pxl;
            float* d = acc[mf][nf];
            float g0 = sGate[pxl], g1 = sGate[pxl + 1];
            float bs0 = defb[co], bs8 = defb[co+8];
            const float* yb0 = g_ybase + (size_t)(b*Cc + co  )*HW + px;
            const float* yb8 = g_ybase + (size_t)(b*Cc + co+8)*HW + px;
            *(float2*)(out + (size_t)(b*Cc + co  )*HW + px) = make_float2(
                (1.0f-g0)*yb0[0] + g0*(d[0]+bs0), (1.0f-g1)*yb0[1] + g1*(d[1]+bs0));
            *(float2*)(out + (size_t)(b*Cc + co+8)*HW + px) = make_float2(
                (1.0f-g0)*yb8[0] + g0*(d[2]+bs8), (1.0f-g1)*yb8[1] + g1*(d[3]+bs8));
        }
    }
}

// ---------------- host launcher ------------------------------------------
extern "C" void kernel_launch(void* const* d_in, const int* in_sizes, int n_in,
                              void* d_out, int out_size) {
    const float* x      = (const float*)d_in[0];
    const float* off_w  = (const float*)d_in[1];
    const float* off_b  = (const float*)d_in[2];
    const float* gw1    = (const float*)d_in[3];
    const float* gb1    = (const float*)d_in[4];
    const float* gw2    = (const float*)d_in[5];
    const float* gb2    = (const float*)d_in[6];
    const float* base_w = (const float*)d_in[7];
    const float* base_b = (const float*)d_in[8];
    const float* def_w  = (const float*)d_in[9];
    const float* def_b  = (const float*)d_in[10];
    float* out = (float*)d_out;

    const int MMA_SMEM = 4*128*ASTR*2;     // 90112 bytes
    cudaFuncSetAttribute(conv_mma,     cudaFuncAttributeMaxDynamicSharedMemorySize, MMA_SMEM);
    cudaFuncSetAttribute(conv_aux_mma, cudaFuncAttributeMaxDynamicSharedMemorySize, MMA_SMEM);
    cudaFuncSetAttribute(deform_mma,   cudaFuncAttributeMaxDynamicSharedMemorySize, MMA_SMEM);

    transpose_k<<<dim3(HW/32, Cc/32, Bb), dim3(32, 8)>>>(x);     // 1
    wprep_k<<<(18*8192 + 255)/256, 256>>>(base_w);               // 2
    wprepD_k<<<(18*8192 + 255)/256, 256>>>(def_w);               // 3
    conv_mma<<<Bb*256, 256, MMA_SMEM>>>(base_b);                 // 4  <- profiled
    fft_rows_k<<<Bb*Cc*Hh/4, 512>>>(x);                          // 5
    fft_cols_k<<<Bb*KWF*16, 512>>>();                            // 6
    reduce_feh_k<<<Bb*KWF, 128>>>();                             // 7
    resize_fe_k<<<(Bb*HW + 255)/256, 256>>>();                   // 8
    auxtail_k<<<(Bb*HW + 255)/256, 256>>>();                     // 9
    wprepA_k<<<(27*8192 + 255)/256, 256>>>(off_w, off_b, gw1, gb1); // 10
    conv_aux_mma<<<Bb*256, 256, MMA_SMEM>>>();                   // 11
    deform_mma<<<Bb*256, 256, MMA_SMEM>>>(def_b, gw2, gb2, out); // 12
}

// round 15
// speedup vs baseline: 1.0178x; 1.0178x over previous
#include <cuda_runtime.h>
#include <cuda_bf16.h>
#include <math.h>

#define PI_F 3.14159265358979323846f
#define Bb   2
#define Cc   128
#define Hh   128
#define Ww   256
#define HW   32768
#define AUXC 133
#define KWF  129
#define ASTR 88
#define ABUF (128*ASTR*2)          // 22528 bytes per operand buffer
#define STAGE (4*ABUF)             // 90112 bytes per pipeline stage

__device__ float2 g_R[Bb*KWF*Cc*Hh];
__device__ float  g_part[Bb*KWF*64*128];
__device__ float  g_feh[Bb*Hh*KWF];
__device__ float  g_fe[Bb*HW];
__device__ float  g_off[Bb*18*HW];
__device__ float  g_gbuf[Bb*66*HW];
__device__ float  g_ybase[Bb*Cc*HW];
__device__ float  g_xT[Bb*HW*Cc];
__device__ float  g_bF[96];
__device__ __align__(16) __nv_bfloat16 g_xbh[(size_t)Bb*HW*Cc];
__device__ __align__(16) __nv_bfloat16 g_xbl[(size_t)Bb*HW*Cc];
__device__ __align__(16) __nv_bfloat16 g_ath[(size_t)Bb*HW*16];
__device__ __align__(16) __nv_bfloat16 g_atl[(size_t)Bb*HW*16];
__device__ __align__(16) __nv_bfloat16 g_WBh[18*8192];
__device__ __align__(16) __nv_bfloat16 g_WBl[18*8192];
__device__ __align__(16) __nv_bfloat16 g_WDh[18*8192];
__device__ __align__(16) __nv_bfloat16 g_WDl[18*8192];
__device__ __align__(16) __nv_bfloat16 g_WAh[27*8192];
__device__ __align__(16) __nv_bfloat16 g_WAl[27*8192];

__device__ __forceinline__ unsigned smem_u32(const void* p){
    unsigned r;
    asm("{.reg .u64 t; cvta.to.shared.u64 t, %1; cvt.u32.u64 %0, t;}" : "=r"(r) : "l"(p));
    return r;
}
__device__ __forceinline__ void ldsm4(unsigned* r, unsigned a){
    asm volatile("ldmatrix.sync.aligned.m8n8.x4.shared.b16 {%0,%1,%2,%3}, [%4];"
        : "=r"(r[0]),"=r"(r[1]),"=r"(r[2]),"=r"(r[3]) : "r"(a));
}
__device__ __forceinline__ void mma16816(float* d, const unsigned* a, unsigned b0, unsigned b1){
    asm volatile("mma.sync.aligned.m16n8k16.row.col.f32.bf16.bf16.f32 "
        "{%0,%1,%2,%3}, {%4,%5,%6,%7}, {%8,%9}, {%0,%1,%2,%3};"
        : "+f"(d[0]),"+f"(d[1]),"+f"(d[2]),"+f"(d[3])
        : "r"(a[0]),"r"(a[1]),"r"(a[2]),"r"(a[3]), "r"(b0),"r"(b1));
}
__device__ __forceinline__ void bsplit2(float v, __nv_bfloat16& h, __nv_bfloat16& l){
    h = __float2bfloat16(v);
    l = __float2bfloat16(v - __bfloat162float(h));
}
__device__ __forceinline__ void cpa16(unsigned dst, const void* src, int sz){
    asm volatile("cp.async.cg.shared.global [%0], [%1], 16, %2;"
                 :: "r"(dst), "l"(src), "r"(sz));
}
__device__ __forceinline__ void cpcommit(){ asm volatile("cp.async.commit_group;"); }
__device__ __forceinline__ void cpwait0(){ asm volatile("cp.async.wait_group 0;"); }

// ---------------- FFT over W: 4 rows per 512-thread CTA ------------------
__global__ void __launch_bounds__(512) fft_rows_k(const float* __restrict__ x) {
    __shared__ float2 sm[4][256];
    __shared__ float2 tw[128];
    int tid = threadIdx.x;
    int f = tid >> 7, t = tid & 127;
    int r = blockIdx.x*4 + f;
    int m = r & (Hh-1), c = (r >> 7) & (Cc-1), b = r >> 14;
    if (tid < 128) {
        float ang = -2.0f*PI_F*(float)tid/256.0f;
        tw[tid] = make_float2(cosf(ang), sinf(ang));
    }
    const float* row = x + ((size_t)(b*Cc + c)*Hh + m)*Ww;
    for (int i = t; i < 256; i += 128)
        sm[f][__brev(i) >> 24] = make_float2(row[i], 0.0f);
    __syncthreads();
#pragma unroll
    for (int s = 1; s <= 8; s++) {
        int half = 1 << (s-1);
        int pos = t & (half-1);
        int i0 = ((t >> (s-1)) << s) | pos, i1 = i0 + half;
        float2 w = tw[pos << (8-s)];
        float2 a = sm[f][i0], bv = sm[f][i1];
        float2 tt = make_float2(bv.x*w.x - bv.y*w.y, bv.x*w.y + bv.y*w.x);
        sm[f][i0] = make_float2(a.x + tt.x, a.y + tt.y);
        sm[f][i1] = make_float2(a.x - tt.x, a.y - tt.y);
        __syncthreads();
    }
    g_R[((size_t)(b*KWF + t)*Cc + c)*Hh + m] = sm[f][t];
    if (t == 0)
        g_R[((size_t)(b*KWF + 128)*Cc + c)*Hh + m] = sm[f][128];
}

// ---------------- FFT over H: 4 channel-pairs per 512-thread CTA ---------
__global__ void __launch_bounds__(512) fft_cols_k(void) {
    __shared__ float2 sm[8][128];
    __shared__ float2 tw[64];
    __shared__ float  mg[4][128];
    int bid = blockIdx.x;
    int t16 = bid & 15;
    int kw = (bid >> 4) % KWF;
    int b  = bid / (16*KWF);
    int tid = threadIdx.x;
    int ch = tid >> 6, lane = tid & 63;
    int cp = t16*4 + (ch >> 1);
    int c  = cp*2 + (ch & 1);
    if (tid < 64) {
        float ang = -2.0f*PI_F*(float)tid/128.0f;
        tw[tid] = make_float2(cosf(ang), sinf(ang));
    }
    const float2* base = g_R + (size_t)(b*KWF + kw)*Cc*Hh + c*Hh;
#pragma unroll
    for (int i = lane; i < 128; i += 64)
        sm[ch][__brev(i) >> 25] = base[i];
    __syncthreads();
#pragma unroll
    for (int s = 1; s <= 7; s++) {
        int half = 1 << (s-1);
        int pos = lane & (half-1);
        int i0 = ((lane >> (s-1)) << s) | pos, i1 = i0 + half;
        float2 w = tw[pos << (7-s)];
        float2 a = sm[ch][i0], bv = sm[ch][i1];
        float2 t = make_float2(bv.x*w.x - bv.y*w.y, bv.x*w.y + bv.y*w.x);
        sm[ch][i0] = make_float2(a.x + t.x, a.y + t.y);
        sm[ch][i1] = make_float2(a.x - t.x, a.y - t.y);
        __syncthreads();
    }
    if ((ch & 1) == 0)
        for (int i = lane; i < 128; i += 64) {
            float2 X = sm[ch][i];
            mg[ch >> 1][i] = sqrtf(X.x*X.x + X.y*X.y);
        }
    __syncthreads();
    if ((ch & 1) == 1)
        for (int i = lane; i < 128; i += 64) {
            float2 X = sm[ch][i];
            g_part[((size_t)(b*KWF + kw)*64 + cp)*128 + i] =
                mg[ch >> 1][i] + sqrtf(X.x*X.x + X.y*X.y);
        }
}

__global__ void reduce_feh_k(void) {
    int bid = blockIdx.x;
    int kw = bid % KWF, b = bid / KWF;
    int kh = threadIdx.x;
    float s = 0.0f;
    const float* p = g_part + (size_t)bid*64*128 + kh;
#pragma unroll 8
    for (int cp = 0; cp < 64; cp++) s += p[cp*128];
    g_feh[(size_t)(b*Hh + kh)*KWF + kw] = s * (1.0f/(128.0f*sqrtf((float)HW)));
}

__global__ void resize_fe_k(void) {
    int idx = blockIdx.x*blockDim.x + threadIdx.x;
    if (idx >= Bb*HW) return;
    int w = idx & (Ww-1), h = (idx >> 8) & (Hh-1), b = idx >> 15;
    float px = ((float)w + 0.5f)*(129.0f/256.0f) - 0.5f;
    float x0f = floorf(px);
    float f = px - x0f;
    int x0 = min(max((int)x0f, 0), 128), x1 = min(max((int)x0f + 1, 0), 128);
    const float* r = g_feh + (size_t)(b*Hh + h)*KWF;
    g_fe[idx] = r[x0]*(1.0f-f) + r[x1]*f;
}

// ---------------- aux tail: 16 NHWC channels -----------------------------
__global__ void auxtail_k(void) {
    int idx = blockIdx.x*blockDim.x + threadIdx.x;
    if (idx >= Bb*HW) return;
    int w = idx & (Ww-1), h = (idx >> 8) & (Hh-1);
    float th = -PI_F + (2.0f*PI_F/255.0f)*(float)w;
    float ph = -0.5f*PI_F + (PI_F/127.0f)*(float)h;
    float v[16] = {sinf(th), cosf(th), sinf(ph), cosf(ph), g_fe[idx],
                   0,0,0,0,0,0,0,0,0,0,0};
    __nv_bfloat16* oh = g_ath + (size_t)idx*16;
    __nv_bfloat16* ol = g_atl + (size_t)idx*16;
#pragma unroll
    for (int k = 0; k < 16; k++) {
        __nv_bfloat16 hb, lb; bsplit2(v[k], hb, lb);
        oh[k] = hb; ol[k] = lb;
    }
}

// ---------------- transpose + bf16 hi/lo split ---------------------------
__global__ void transpose_k(const float* __restrict__ x) {
    __shared__ float t[32][33];
    int b = blockIdx.z, p0 = blockIdx.x*32, c0 = blockIdx.y*32;
    int tx = threadIdx.x, ty = threadIdx.y;
#pragma unroll
    for (int j = 0; j < 4; j++)
        t[ty + j*8][tx] = x[(size_t)(b*Cc + c0 + ty + j*8)*HW + p0 + tx];
    __syncthreads();
#pragma unroll
    for (int j = 0; j < 4; j++) {
        float v = t[tx][ty + j*8];
        size_t o = (size_t)(b*HW + p0 + ty + j*8)*Cc + c0 + tx;
        g_xT[o] = v;
        __nv_bfloat16 hb, lb; bsplit2(v, hb, lb);
        g_xbh[o] = hb; g_xbl[o] = lb;
    }
}

// ---------------- weight preps -------------------------------------------
__global__ void wprep_k(const float* __restrict__ bw) {
    int idx = blockIdx.x*blockDim.x + threadIdx.x;
    if (idx >= 18*8192) return;
    int c = idx >> 13, r = idx & 8191;
    int co = r >> 6, k = r & 63;
    int kk = c >> 1, ci = (c & 1)*64 + k;
    float v = bw[(size_t)(co*Cc + ci)*9 + kk];
    __nv_bfloat16 hb, lb; bsplit2(v, hb, lb);
    g_WBh[idx] = hb; g_WBl[idx] = lb;
}
__global__ void wprepD_k(const float* __restrict__ dw) {
    int idx = blockIdx.x*blockDim.x + threadIdx.x;
    if (idx >= 18*8192) return;
    int c = idx >> 13, r = idx & 8191;
    int co = r >> 6, k = r & 63;
    int kk = c >> 1, ci = (c & 1)*64 + k;
    float v = dw[(size_t)(co*Cc + ci)*9 + kk];
    __nv_bfloat16 hb, lb; bsplit2(v, hb, lb);
    g_WDh[idx] = hb; g_WDl[idx] = lb;
}
__global__ void wprepA_k(const float* __restrict__ ow, const float* __restrict__ ob,
                         const float* __restrict__ gw, const float* __restrict__ gb) {
    int idx = blockIdx.x*blockDim.x + threadIdx.x;
    if (idx < 96) g_bF[idx] = (idx < 18) ? ob[idx] : (idx < 84 ? gb[idx-18] : 0.0f);
    if (idx >= 27*8192) return;
    int c = idx >> 13, r = idx & 8191;
    int co = r >> 6, k = r & 63;
    int tap = c / 3, sub = c % 3;
    int ci = sub*64 + k;
    float v = 0.0f;
    if (co < 84 && ci < AUXC)
        v = (co < 18) ? ow[(size_t)(co*AUXC + ci)*9 + tap]
                      : gw[(size_t)((co-18)*AUXC + ci)*9 + tap];
    __nv_bfloat16 hb, lb; bsplit2(v, hb, lb);
    g_WAh[idx] = hb; g_WAl[idx] = lb;
}

// ---------------- async fill helpers -------------------------------------
__device__ __forceinline__ void fill_conv(unsigned sbase, int c, int b, int h, int w0,
        const __nv_bfloat16* Wh, const __nv_bfloat16* Wl, int tid) {
    int kk = c >> 1;
    int dy = kk/3 - 1, dx = kk%3 - 1;
    int ci0 = (c & 1)*64;
    for (int i = tid; i < 2048; i += 256) {
        int buf = i >> 10, idx = i & 1023;
        int row = idx >> 3, seg = idx & 7;
        unsigned dst = sbase + buf*ABUF + (unsigned)(row*ASTR + seg*8)*2;
        cpa16(dst, (buf ? Wl : Wh) + (size_t)c*8192 + row*64 + seg*8, 16);
    }
    int sh = h + dy;
    for (int i = tid; i < 2048; i += 256) {
        int buf = i >> 10, idx = i & 1023;
        int p = idx >> 3, seg = idx & 7;
        int sw = w0 + p + dx;
        bool ok = (sw >= 0 && sw < Ww && sh >= 0 && sh < Hh);
        int swc = ok ? sw : 0, shc = ok ? sh : 0;
        unsigned dst = sbase + 2*ABUF + buf*ABUF + (unsigned)(p*ASTR + seg*8)*2;
        cpa16(dst, (buf ? g_xbl : g_xbh) +
              ((size_t)(b*HW) + shc*Ww + swc)*Cc + ci0 + seg*8, ok ? 16 : 0);
    }
    cpcommit();
}
__device__ __forceinline__ void fill_aux(unsigned sbase, int c, int b, int h, int w0, int tid) {
    int tap = c / 3, sub = c - tap*3;
    int dy = tap/3 - 1, dx = tap%3 - 1;
    for (int i = tid; i < 2048; i += 256) {
        int buf = i >> 10, idx = i & 1023;
        int row = idx >> 3, seg = idx & 7;
        unsigned dst = sbase + buf*ABUF + (unsigned)(row*ASTR + seg*8)*2;
        cpa16(dst, (buf ? g_WAl : g_WAh) + (size_t)c*8192 + row*64 + seg*8, 16);
    }
    int sh = h + dy;
    if (sub < 2) {
        int ci0 = sub*64;
        for (int i = tid; i < 2048; i += 256) {
            int buf = i >> 10, idx = i & 1023;
            int p = idx >> 3, seg = idx & 7;
            int sw = w0 + p + dx;
            bool ok = (sw >= 0 && sw < Ww && sh >= 0 && sh < Hh);
            int swc = ok ? sw : 0, shc = ok ? sh : 0;
            unsigned dst = sbase + 2*ABUF + buf*ABUF + (unsigned)(p*ASTR + seg*8)*2;
            cpa16(dst, (buf ? g_xbl : g_xbh) +
                  ((size_t)(b*HW) + shc*Ww + swc)*Cc + ci0 + seg*8, ok ? 16 : 0);
        }
    } else {
        for (int i = tid; i < 512; i += 256) {
            int buf = i >> 8, idx = i & 255;
            int p = idx >> 1, seg = idx & 1;
            int sw = w0 + p + dx;
            bool ok = (sw >= 0 && sw < Ww && sh >= 0 && sh < Hh);
            int swc = ok ? sw : 0, shc = ok ? sh : 0;
            unsigned dst = sbase + 2*ABUF + buf*ABUF + (unsigned)(p*ASTR + seg*8)*2;
            cpa16(dst, (buf ? g_atl : g_ath) +
                  ((size_t)(b*HW) + shc*Ww + swc)*16 + seg*8, ok ? 16 : 0);
        }
    }
    cpcommit();
}

// ---------------- mma.sync base conv, cp.async double-buffered -----------
__global__ void __launch_bounds__(256) conv_mma(const float* __restrict__ bias) {
    extern __shared__ __align__(16) unsigned char dsm[];
    unsigned s0 = smem_u32(dsm);
    int tid = threadIdx.x;
    int wid = tid >> 5, lane = tid & 31;
    int co0 = (wid & 1)*64, pxo = (wid >> 1)*32;
    int blk = blockIdx.x;
    int b = blk >> 8;
    int px0 = (blk & 255) * 128;
    int h = px0 >> 8, w0 = px0 & 255;
    int r15 = lane & 15, r16 = (lane >> 4)*8;

    float acc[4][4][4];
#pragma unroll
    for (int mf = 0; mf < 4; mf++)
#pragma unroll
        for (int nf = 0; nf < 4; nf++)
#pragma unroll
            for (int q = 0; q < 4; q++) acc[mf][nf][q] = 0.0f;

    fill_conv(s0, 0, b, h, w0, g_WBh, g_WBl, tid);
    for (int c = 0; c < 18; c++) {
        cpwait0();
        __syncthreads();
        if (c + 1 < 18)
            fill_conv(s0 + ((c+1)&1)*STAGE, c+1, b, h, w0, g_WBh, g_WBl, tid);
        unsigned sb = s0 + (c&1)*STAGE;
        unsigned Ah_ = sb, Al_ = sb + ABUF, Bh_ = sb + 2*ABUF, Bl_ = sb + 3*ABUF;
#pragma unroll
        for (int ks = 0; ks < 4; ks++) {
            unsigned bh[2][4], bl[2][4];
#pragma unroll
            for (int nh = 0; nh < 2; nh++) {
                ldsm4(bh[nh], Bh_ + (unsigned)((pxo + nh*16 + r15)*ASTR + ks*16 + r16)*2);
                ldsm4(bl[nh], Bl_ + (unsigned)((pxo + nh*16 + r15)*ASTR + ks*16 + r16)*2);
            }
#pragma unroll
            for (int mf = 0; mf < 4; mf++) {
                unsigned ah[4], al[4];
                ldsm4(ah, Ah_ + (unsigned)((co0 + mf*16 + r15)*ASTR + ks*16 + r16)*2);
                ldsm4(al, Al_ + (unsigned)((co0 + mf*16 + r15)*ASTR + ks*16 + r16)*2);
#pragma unroll
                for (int nf = 0; nf < 4; nf++) {
                    int nh = nf >> 1, sel = nf & 1;
                    mma16816(acc[mf][nf], ah, bh[nh][sel], bh[nh][sel+2]);
                    mma16816(acc[mf][nf], ah, bl[nh][sel], bl[nh][sel+2]);
                    mma16816(acc[mf][nf], al, bh[nh][sel], bh[nh][sel+2]);
                }
            }
        }
        __syncthreads();
    }
    int gid = lane >> 2, t4 = lane & 3;
#pragma unroll
    for (int mf = 0; mf < 4; mf++) {
#pragma unroll
        for (int nf = 0; nf < 4; nf++) {
            int co = co0 + mf*16 + gid;
            int px = px0 + pxo + nf*8 + t4*2;
            float* d = acc[mf][nf];
            *(float2*)(g_ybase + (size_t)(b*Cc + co  )*HW + px) =
                make_float2(d[0] + bias[co],   d[1] + bias[co]);
            *(float2*)(g_ybase + (size_t)(b*Cc + co+8)*HW + px) =
                make_float2(d[2] + bias[co+8], d[3] + bias[co+8]);
        }
    }
}

// ---------------- mma.sync aux conv, cp.async double-buffered ------------
__global__ void __launch_bounds__(256) conv_aux_mma(void) {
    extern __shared__ __align__(16) unsigned char dsm[];
    unsigned s0 = smem_u32(dsm);
    int tid = threadIdx.x;
    int wid = tid >> 5, lane = tid & 31;
    int co0 = (wid & 1)*64, pxo = (wid >> 1)*32;
    int blk = blockIdx.x;
    int b = blk >> 8;
    int px0 = (blk & 255) * 128;
    int h = px0 >> 8, w0 = px0 & 255;
    int r15 = lane & 15, r16 = (lane >> 4)*8;

    float acc[4][4][4];
#pragma unroll
    for (int mf = 0; mf < 4; mf++)
#pragma unroll
        for (int nf = 0; nf < 4; nf++)
#pragma unroll
            for (int q = 0; q < 4; q++) acc[mf][nf][q] = 0.0f;

    fill_aux(s0, 0, b, h, w0, tid);
    for (int c = 0; c < 27; c++) {
        cpwait0();
        __syncthreads();
        if (c + 1 < 27)
            fill_aux(s0 + ((c+1)&1)*STAGE, c+1, b, h, w0, tid);
        unsigned sb = s0 + (c&1)*STAGE;
        unsigned Ah_ = sb, Al_ = sb + ABUF, Bh_ = sb + 2*ABUF, Bl_ = sb + 3*ABUF;
        int sub = c - (c/3)*3;
        int nks = (sub < 2) ? 4 : 1;
        for (int ks = 0; ks < nks; ks++) {
            unsigned bh[2][4], bl[2][4];
#pragma unroll
            for (int nh = 0; nh < 2; nh++) {
                ldsm4(bh[nh], Bh_ + (unsigned)((pxo + nh*16 + r15)*ASTR + ks*16 + r16)*2);
                ldsm4(bl[nh], Bl_ + (unsigned)((pxo + nh*16 + r15)*ASTR + ks*16 + r16)*2);
            }
#pragma unroll
            for (int mf = 0; mf < 4; mf++) {
                unsigned ah[4], al[4];
                ldsm4(ah, Ah_ + (unsigned)((co0 + mf*16 + r15)*ASTR + ks*16 + r16)*2);
                ldsm4(al, Al_ + (unsigned)((co0 + mf*16 + r15)*ASTR + ks*16 + r16)*2);
#pragma unroll
                for (int nf = 0; nf < 4; nf++) {
                    int nh = nf >> 1, sel = nf & 1;
                    mma16816(acc[mf][nf], ah, bh[nh][sel], bh[nh][sel+2]);
                    mma16816(acc[mf][nf], ah, bl[nh][sel], bl[nh][sel+2]);
                    mma16816(acc[mf][nf], al, bh[nh][sel], bh[nh][sel+2]);
                }
            }
        }
        __syncthreads();
    }
    int gid = lane >> 2, t4 = lane & 3;
#pragma unroll
    for (int mf = 0; mf < 4; mf++) {
#pragma unroll
        for (int nf = 0; nf < 4; nf++) {
            int px = px0 + pxo + nf*8 + t4*2;
            float* d = acc[mf][nf];
#pragma unroll
            for (int half = 0; half < 2; half++) {
                int co = co0 + mf*16 + gid + half*8;
                float v0 = d[half*2] + g_bF[co], v1 = d[half*2+1] + g_bF[co];
                if (co < 18) {
                    *(float2*)(g_off + (size_t)(b*18 + co)*HW + px) = make_float2(v0, v1);
                } else if (co < 84) {
                    *(float2*)(g_gbuf + (size_t)(b*66 + co - 18)*HW + px) =
                        make_float2(fmaxf(v0, 0.0f), fmaxf(v1, 0.0f));
                }
            }
        }
    }
}

// ---------------- mma.sync deform GEMM + fused gate + blend --------------
__global__ void __launch_bounds__(256) deform_mma(
        const float* __restrict__ defb, const float* __restrict__ gw2,
        const float* __restrict__ gb2, float* __restrict__ out) {
    extern __shared__ __align__(16) unsigned char dsm[];
    __nv_bfloat16* Ah = (__nv_bfloat16*)dsm;
    __nv_bfloat16* Al = Ah + 128*ASTR;
    __nv_bfloat16* Bh = Al + 128*ASTR;
    __nv_bfloat16* Bl = Bh + 128*ASTR;
    __shared__ int   sC[4][128];
    __shared__ float sWt[4][128];
    __shared__ float sGate[128];
    int tid = threadIdx.x;
    int wid = tid >> 5, lane = tid & 31;
    int co0 = (wid & 1)*64, pxo = (wid >> 1)*32;
    int blk = blockIdx.x;
    int b = blk >> 8;
    int px0 = (blk & 255) * 128;
    int r15 = lane & 15, r16 = (lane >> 4)*8;

    if (tid < 128) {
        int pp = px0 + tid;
        float s = gb2[0];
#pragma unroll 6
        for (int c = 0; c < 66; c++)
            s = fmaf(g_gbuf[(size_t)(b*66 + c)*HW + pp], gw2[c], s);
        sGate[tid] = 1.0f / (1.0f + __expf(-s));
    }

    float acc[4][4][4];
#pragma unroll
    for (int mf = 0; mf < 4; mf++)
#pragma unroll
        for (int nf = 0; nf < 4; nf++)
#pragma unroll
            for (int q = 0; q < 4; q++) acc[mf][nf][q] = 0.0f;

    for (int c = 0; c < 18; c++) {
        int kk = c >> 1;
        int ci0 = (c & 1)*64;
        __syncthreads();
        if ((c & 1) == 0 && tid < 128) {
            int pp = px0 + tid;
            int hh = pp >> 8, ww = pp & (Ww-1);
            float fpx = (float)ww + g_off[(size_t)(b*18 + 2*kk    )*HW + pp];
            float fpy = (float)hh + g_off[(size_t)(b*18 + 2*kk + 1)*HW + pp];
            float fx0 = floorf(fpx), fy0 = floorf(fpy);
            int X0 = (int)fx0, Y0 = (int)fy0;
            float fx = fpx - fx0, fy = fpy - fy0;
            float w00 = (1.0f-fx)*(1.0f-fy), w10 = fx*(1.0f-fy);
            float w01 = (1.0f-fx)*fy,        w11 = fx*fy;
            if (X0   < 0 || X0   >= Ww) { w00 = 0.0f; w01 = 0.0f; }
            if (X0+1 < 0 || X0+1 >= Ww) { w10 = 0.0f; w11 = 0.0f; }
            if (Y0   < 0 || Y0   >= Hh) { w00 = 0.0f; w10 = 0.0f; }
            if (Y0+1 < 0 || Y0+1 >= Hh) { w01 = 0.0f; w11 = 0.0f; }
            sC[0][tid] = min(max(X0,   0), Ww-1);
            sC[1][tid] = min(max(X0+1, 0), Ww-1);
            sC[2][tid] = min(max(Y0,   0), Hh-1);
            sC[3][tid] = min(max(Y0+1, 0), Hh-1);
            sWt[0][tid] = w00; sWt[1][tid] = w10; sWt[2][tid] = w01; sWt[3][tid] = w11;
        }
        __syncthreads();
        for (int i = tid; i < 2048; i += 256) {
            int buf = i >> 10, idx = i & 1023;
            int row = idx >> 3, seg = idx & 7;
            *((float4*)((buf ? Al : Ah) + row*ASTR) + seg) =
                *((const float4*)((buf ? g_WDl : g_WDh) + (size_t)c*8192 + row*64) + seg);
        }
        for (int i = tid; i < 2048; i += 256) {
            int p = i >> 4, g = i & 15;
            int cx0 = sC[0][p], cx1 = sC[1][p], cy0 = sC[2][p], cy1 = sC[3][p];
            float w00 = sWt[0][p], w10 = sWt[1][p], w01 = sWt[2][p], w11 = sWt[3][p];
            size_t base = (size_t)(b*HW)*Cc + (size_t)(ci0 + g*4);
            float4 a00 = *(const float4*)(g_xT + base + (size_t)(cy0*Ww + cx0)*Cc);
            float4 a10 = *(const float4*)(g_xT + base + (size_t)(cy0*Ww + cx1)*Cc);
            float4 a01 = *(const float4*)(g_xT + base + (size_t)(cy1*Ww + cx0)*Cc);
            float4 a11 = *(const float4*)(g_xT + base + (size_t)(cy1*Ww + cx1)*Cc);
            float4 r;
            r.x = w00*a00.x + w10*a10.x + w01*a01.x + w11*a11.x;
            r.y = w00*a00.y + w10*a10.y + w01*a01.y + w11*a11.y;
            r.z = w00*a00.z + w10*a10.z + w01*a01.z + w11*a11.z;
            r.w = w00*a00.w + w10*a10.w + w01*a01.w + w11*a11.w;
            __nv_bfloat16 h0, l0, h1, l1, h2, l2, h3, l3;
            bsplit2(r.x, h0, l0); bsplit2(r.y, h1, l1);
            bsplit2(r.z, h2, l2); bsplit2(r.w, h3, l3);
            __nv_bfloat162* dh = (__nv_bfloat162*)(Bh + p*ASTR + g*4);
            dh[0] = __nv_bfloat162(h0, h1); dh[1] = __nv_bfloat162(h2, h3);
            __nv_bfloat162* dl = (__nv_bfloat162*)(Bl + p*ASTR + g*4);
            dl[0] = __nv_bfloat162(l0, l1); dl[1] = __nv_bfloat162(l2, l3);
        }
        __syncthreads();
#pragma unroll
        for (int ks = 0; ks < 4; ks++) {
            unsigned bh[2][4], bl[2][4];
#pragma unroll
            for (int nh = 0; nh < 2; nh++) {
                ldsm4(bh[nh], smem_u32(Bh + (pxo + nh*16 + r15)*ASTR + ks*16 + r16));
                ldsm4(bl[nh], smem_u32(Bl + (pxo + nh*16 + r15)*ASTR + ks*16 + r16));
            }
#pragma unroll
            for (int mf = 0; mf < 4; mf++) {
                unsigned ah[4], al[4];
                ldsm4(ah, smem_u32(Ah + (co0 + mf*16 + r15)*ASTR + ks*16 + r16));
                ldsm4(al, smem_u32(Al + (co0 + mf*16 + r15)*ASTR + ks*16 + r16));
#pragma unroll
                for (int nf = 0; nf < 4; nf++) {
                    int nh = nf >> 1, sel = nf & 1;
                    mma16816(acc[mf][nf], ah, bh[nh][sel], bh[nh][sel+2]);
                    mma16816(acc[mf][nf], ah, bl[nh][sel], bl[nh][sel+2]);
                    mma16816(acc[mf][nf], al, bh[nh][sel], bh[nh][sel+2]);
                }
            }
        }
    }
    int gid = lane >> 2, t4 = lane & 3;
#pragma unroll
    for (int mf = 0; mf < 4; mf++) {
#pragma unroll
        for (int nf = 0; nf < 4; nf++) {
            int co = co0 + mf*16 + gid;
            int pxl = pxo + nf*8 + t4*2;
            int px = px0 + pxl;
            float* d = acc[mf][nf];
            float g0 = sGate[pxl], g1 = sGate[pxl + 1];
            float bs0 = defb[co], bs8 = defb[co+8];
            const float* yb0 = g_ybase + (size_t)(b*Cc + co  )*HW + px;
            const float* yb8 = g_ybase + (size_t)(b*Cc + co+8)*HW + px;
            *(float2*)(out + (size_t)(b*Cc + co  )*HW + px) = make_float2(
                (1.0f-g0)*yb0[0] + g0*(d[0]+bs0), (1.0f-g1)*yb0[1] + g1*(d[1]+bs0));
            *(float2*)(out + (size_t)(b*Cc + co+8)*HW + px) = make_float2(
                (1.0f-g0)*yb8[0] + g0*(d[2]+bs8), (1.0f-g1)*yb8[1] + g1*(d[3]+bs8));
        }
    }
}

// ---------------- host launcher ------------------------------------------
extern "C" void kernel_launch(void* const* d_in, const int* in_sizes, int n_in,
                              void* d_out, int out_size) {
    const float* x      = (const float*)d_in[0];
    const float* off_w  = (const float*)d_in[1];
    const float* off_b  = (const float*)d_in[2];
    const float* gw1    = (const float*)d_in[3];
    const float* gb1    = (const float*)d_in[4];
    const float* gw2    = (const float*)d_in[5];
    const float* gb2    = (const float*)d_in[6];
    const float* base_w = (const float*)d_in[7];
    const float* base_b = (const float*)d_in[8];
    const float* def_w  = (const float*)d_in[9];
    const float* def_b  = (const float*)d_in[10];
    float* out = (float*)d_out;

    const int PIPE_SMEM = 2*STAGE;   // 180224 bytes
    const int ONE_SMEM  = STAGE;     // 90112 bytes
    cudaFuncSetAttribute(conv_mma,     cudaFuncAttributeMaxDynamicSharedMemorySize, PIPE_SMEM);
    cudaFuncSetAttribute(conv_aux_mma, cudaFuncAttributeMaxDynamicSharedMemorySize, PIPE_SMEM);
    cudaFuncSetAttribute(deform_mma,   cudaFuncAttributeMaxDynamicSharedMemorySize, ONE_SMEM);

    transpose_k<<<dim3(HW/32, Cc/32, Bb), dim3(32, 8)>>>(x);        // 1
    wprep_k<<<(18*8192 + 255)/256, 256>>>(base_w);                  // 2
    wprepD_k<<<(18*8192 + 255)/256, 256>>>(def_w);                  // 3
    conv_mma<<<Bb*256, 256, PIPE_SMEM>>>(base_b);                   // 4  <- profiled
    fft_rows_k<<<Bb*Cc*Hh/4, 512>>>(x);                             // 5
    fft_cols_k<<<Bb*KWF*16, 512>>>();                               // 6
    reduce_feh_k<<<Bb*KWF, 128>>>();                                // 7
    resize_fe_k<<<(Bb*HW + 255)/256, 256>>>();                      // 8
    auxtail_k<<<(Bb*HW + 255)/256, 256>>>();                        // 9
    wprepA_k<<<(27*8192 + 255)/256, 256>>>(off_w, off_b, gw1, gb1); // 10
    conv_aux_mma<<<Bb*256, 256, PIPE_SMEM>>>();                     // 11
    deform_mma<<<Bb*256, 256, ONE_SMEM>>>(def_b, gw2, gb2, out);    // 12
}

// round 16
// speedup vs baseline: 1.0303x; 1.0123x over previous
#include <cuda_runtime.h>
#include <cuda_bf16.h>
#include <math.h>

#define PI_F 3.14159265358979323846f
#define Bb   2
#define Cc   128
#define Hh   128
#define Ww   256
#define HW   32768
#define AUXC 133
#define KWF  129
#define ASTR 88                      // deform kernel layout (K=64)
#define ASTR2 40                     // pipelined conv layout (K=32)
#define ABUF2 (128*ASTR2*2)          // 10240 B per operand buffer
#define STAGE2 (4*ABUF2)             // 40960 B per stage
#define PIPE2 (2*STAGE2)             // 81920 B

__device__ float2 g_R[Bb*KWF*Cc*Hh];
__device__ float  g_part[Bb*KWF*64*128];
__device__ float  g_feh[Bb*Hh*KWF];
__device__ float  g_fe[Bb*HW];
__device__ float  g_off[Bb*18*HW];
__device__ float  g_gbuf[Bb*66*HW];
__device__ float  g_ybase[Bb*Cc*HW];
__device__ float  g_xT[Bb*HW*Cc];
__device__ float  g_bF[96];
__device__ __align__(16) __nv_bfloat16 g_xbh[(size_t)Bb*HW*Cc];
__device__ __align__(16) __nv_bfloat16 g_xbl[(size_t)Bb*HW*Cc];
__device__ __align__(16) __nv_bfloat16 g_ath[(size_t)Bb*HW*16];
__device__ __align__(16) __nv_bfloat16 g_atl[(size_t)Bb*HW*16];
__device__ __align__(16) __nv_bfloat16 g_WBh[18*8192];
__device__ __align__(16) __nv_bfloat16 g_WBl[18*8192];
__device__ __align__(16) __nv_bfloat16 g_WDh[18*8192];
__device__ __align__(16) __nv_bfloat16 g_WDl[18*8192];
__device__ __align__(16) __nv_bfloat16 g_WAh[27*8192];
__device__ __align__(16) __nv_bfloat16 g_WAl[27*8192];

__device__ __forceinline__ unsigned smem_u32(const void* p){
    unsigned r;
    asm("{.reg .u64 t; cvta.to.shared.u64 t, %1; cvt.u32.u64 %0, t;}" : "=r"(r) : "l"(p));
    return r;
}
__device__ __forceinline__ void ldsm4(unsigned* r, unsigned a){
    asm volatile("ldmatrix.sync.aligned.m8n8.x4.shared.b16 {%0,%1,%2,%3}, [%4];"
        : "=r"(r[0]),"=r"(r[1]),"=r"(r[2]),"=r"(r[3]) : "r"(a));
}
__device__ __forceinline__ void mma16816(float* d, const unsigned* a, unsigned b0, unsigned b1){
    asm volatile("mma.sync.aligned.m16n8k16.row.col.f32.bf16.bf16.f32 "
        "{%0,%1,%2,%3}, {%4,%5,%6,%7}, {%8,%9}, {%0,%1,%2,%3};"
        : "+f"(d[0]),"+f"(d[1]),"+f"(d[2]),"+f"(d[3])
        : "r"(a[0]),"r"(a[1]),"r"(a[2]),"r"(a[3]), "r"(b0),"r"(b1));
}
__device__ __forceinline__ void bsplit2(float v, __nv_bfloat16& h, __nv_bfloat16& l){
    h = __float2bfloat16(v);
    l = __float2bfloat16(v - __bfloat162float(h));
}
__device__ __forceinline__ void cpa16(unsigned dst, const void* src, int sz){
    asm volatile("cp.async.cg.shared.global [%0], [%1], 16, %2;"
                 :: "r"(dst), "l"(src), "r"(sz));
}
__device__ __forceinline__ void cpcommit(){ asm volatile("cp.async.commit_group;"); }
__device__ __forceinline__ void cpwait0(){ asm volatile("cp.async.wait_group 0;"); }

// ---------------- FFT over W: 4 rows per 512-thread CTA ------------------
__global__ void __launch_bounds__(512) fft_rows_k(const float* __restrict__ x) {
    __shared__ float2 sm[4][256];
    __shared__ float2 tw[128];
    int tid = threadIdx.x;
    int f = tid >> 7, t = tid & 127;
    int r = blockIdx.x*4 + f;
    int m = r & (Hh-1), c = (r >> 7) & (Cc-1), b = r >> 14;
    if (tid < 128) {
        float ang = -2.0f*PI_F*(float)tid/256.0f;
        tw[tid] = make_float2(cosf(ang), sinf(ang));
    }
    const float* row = x + ((size_t)(b*Cc + c)*Hh + m)*Ww;
    for (int i = t; i < 256; i += 128)
        sm[f][__brev(i) >> 24] = make_float2(row[i], 0.0f);
    __syncthreads();
#pragma unroll
    for (int s = 1; s <= 8; s++) {
        int half = 1 << (s-1);
        int pos = t & (half-1);
        int i0 = ((t >> (s-1)) << s) | pos, i1 = i0 + half;
        float2 w = tw[pos << (8-s)];
        float2 a = sm[f][i0], bv = sm[f][i1];
        float2 tt = make_float2(bv.x*w.x - bv.y*w.y, bv.x*w.y + bv.y*w.x);
        sm[f][i0] = make_float2(a.x + tt.x, a.y + tt.y);
        sm[f][i1] = make_float2(a.x - tt.x, a.y - tt.y);
        __syncthreads();
    }
    g_R[((size_t)(b*KWF + t)*Cc + c)*Hh + m] = sm[f][t];
    if (t == 0)
        g_R[((size_t)(b*KWF + 128)*Cc + c)*Hh + m] = sm[f][128];
}

// ---------------- FFT over H: 4 channel-pairs per 512-thread CTA ---------
__global__ void __launch_bounds__(512) fft_cols_k(void) {
    __shared__ float2 sm[8][128];
    __shared__ float2 tw[64];
    __shared__ float  mg[4][128];
    int bid = blockIdx.x;
    int t16 = bid & 15;
    int kw = (bid >> 4) % KWF;
    int b  = bid / (16*KWF);
    int tid = threadIdx.x;
    int ch = tid >> 6, lane = tid & 63;
    int cp = t16*4 + (ch >> 1);
    int c  = cp*2 + (ch & 1);
    if (tid < 64) {
        float ang = -2.0f*PI_F*(float)tid/128.0f;
        tw[tid] = make_float2(cosf(ang), sinf(ang));
    }
    const float2* base = g_R + (size_t)(b*KWF + kw)*Cc*Hh + c*Hh;
#pragma unroll
    for (int i = lane; i < 128; i += 64)
        sm[ch][__brev(i) >> 25] = base[i];
    __syncthreads();
#pragma unroll
    for (int s = 1; s <= 7; s++) {
        int half = 1 << (s-1);
        int pos = lane & (half-1);
        int i0 = ((lane >> (s-1)) << s) | pos, i1 = i0 + half;
        float2 w = tw[pos << (7-s)];
        float2 a = sm[ch][i0], bv = sm[ch][i1];
        float2 t = make_float2(bv.x*w.x - bv.y*w.y, bv.x*w.y + bv.y*w.x);
        sm[ch][i0] = make_float2(a.x + t.x, a.y + t.y);
        sm[ch][i1] = make_float2(a.x - t.x, a.y - t.y);
        __syncthreads();
    }
    if ((ch & 1) == 0)
        for (int i = lane; i < 128; i += 64) {
            float2 X = sm[ch][i];
            mg[ch >> 1][i] = sqrtf(X.x*X.x + X.y*X.y);
        }
    __syncthreads();
    if ((ch & 1) == 1)
        for (int i = lane; i < 128; i += 64) {
            float2 X = sm[ch][i];
            g_part[((size_t)(b*KWF + kw)*64 + cp)*128 + i] =
                mg[ch >> 1][i] + sqrtf(X.x*X.x + X.y*X.y);
        }
}

__global__ void reduce_feh_k(void) {
    int bid = blockIdx.x;
    int kw = bid % KWF, b = bid / KWF;
    int kh = threadIdx.x;
    float s = 0.0f;
    const float* p = g_part + (size_t)bid*64*128 + kh;
#pragma unroll 8
    for (int cp = 0; cp < 64; cp++) s += p[cp*128];
    g_feh[(size_t)(b*Hh + kh)*KWF + kw] = s * (1.0f/(128.0f*sqrtf((float)HW)));
}

__global__ void resize_fe_k(void) {
    int idx = blockIdx.x*blockDim.x + threadIdx.x;
    if (idx >= Bb*HW) return;
    int w = idx & (Ww-1), h = (idx >> 8) & (Hh-1), b = idx >> 15;
    float px = ((float)w + 0.5f)*(129.0f/256.0f) - 0.5f;
    float x0f = floorf(px);
    float f = px - x0f;
    int x0 = min(max((int)x0f, 0), 128), x1 = min(max((int)x0f + 1, 0), 128);
    const float* r = g_feh + (size_t)(b*Hh + h)*KWF;
    g_fe[idx] = r[x0]*(1.0f-f) + r[x1]*f;
}

// ---------------- aux tail: 16 NHWC channels -----------------------------
__global__ void auxtail_k(void) {
    int idx = blockIdx.x*blockDim.x + threadIdx.x;
    if (idx >= Bb*HW) return;
    int w = idx & (Ww-1), h = (idx >> 8) & (Hh-1);
    float th = -PI_F + (2.0f*PI_F/255.0f)*(float)w;
    float ph = -0.5f*PI_F + (PI_F/127.0f)*(float)h;
    float v[16] = {sinf(th), cosf(th), sinf(ph), cosf(ph), g_fe[idx],
                   0,0,0,0,0,0,0,0,0,0,0};
    __nv_bfloat16* oh = g_ath + (size_t)idx*16;
    __nv_bfloat16* ol = g_atl + (size_t)idx*16;
#pragma unroll
    for (int k = 0; k < 16; k++) {
        __nv_bfloat16 hb, lb; bsplit2(v[k], hb, lb);
        oh[k] = hb; ol[k] = lb;
    }
}

// ---------------- transpose + bf16 hi/lo split ---------------------------
__global__ void transpose_k(const float* __restrict__ x) {
    __shared__ float t[32][33];
    int b = blockIdx.z, p0 = blockIdx.x*32, c0 = blockIdx.y*32;
    int tx = threadIdx.x, ty = threadIdx.y;
#pragma unroll
    for (int j = 0; j < 4; j++)
        t[ty + j*8][tx] = x[(size_t)(b*Cc + c0 + ty + j*8)*HW + p0 + tx];
    __syncthreads();
#pragma unroll
    for (int j = 0; j < 4; j++) {
        float v = t[tx][ty + j*8];
        size_t o = (size_t)(b*HW + p0 + ty + j*8)*Cc + c0 + tx;
        g_xT[o] = v;
        __nv_bfloat16 hb, lb; bsplit2(v, hb, lb);
        g_xbh[o] = hb; g_xbl[o] = lb;
    }
}

// ---------------- weight preps -------------------------------------------
__global__ void wprep_k(const float* __restrict__ bw) {
    int idx = blockIdx.x*blockDim.x + threadIdx.x;
    if (idx >= 18*8192) return;
    int c = idx >> 13, r = idx & 8191;
    int co = r >> 6, k = r & 63;
    int kk = c >> 1, ci = (c & 1)*64 + k;
    float v = bw[(size_t)(co*Cc + ci)*9 + kk];
    __nv_bfloat16 hb, lb; bsplit2(v, hb, lb);
    g_WBh[idx] = hb; g_WBl[idx] = lb;
}
__global__ void wprepD_k(const float* __restrict__ dw) {
    int idx = blockIdx.x*blockDim.x + threadIdx.x;
    if (idx >= 18*8192) return;
    int c = idx >> 13, r = idx & 8191;
    int co = r >> 6, k = r & 63;
    int kk = c >> 1, ci = (c & 1)*64 + k;
    float v = dw[(size_t)(co*Cc + ci)*9 + kk];
    __nv_bfloat16 hb, lb; bsplit2(v, hb, lb);
    g_WDh[idx] = hb; g_WDl[idx] = lb;
}
__global__ void wprepA_k(const float* __restrict__ ow, const float* __restrict__ ob,
                         const float* __restrict__ gw, const float* __restrict__ gb) {
    int idx = blockIdx.x*blockDim.x + threadIdx.x;
    if (idx < 96) g_bF[idx] = (idx < 18) ? ob[idx] : (idx < 84 ? gb[idx-18] : 0.0f);
    if (idx >= 27*8192) return;
    int c = idx >> 13, r = idx & 8191;
    int co = r >> 6, k = r & 63;
    int tap = c / 3, sub = c % 3;
    int ci = sub*64 + k;
    float v = 0.0f;
    if (co < 84 && ci < AUXC)
        v = (co < 18) ? ow[(size_t)(co*AUXC + ci)*9 + tap]
                      : gw[(size_t)((co-18)*AUXC + ci)*9 + tap];
    __nv_bfloat16 hb, lb; bsplit2(v, hb, lb);
    g_WAh[idx] = hb; g_WAl[idx] = lb;
}

// ---------------- K=32 async fills ---------------------------------------
__device__ __forceinline__ void fill_conv32(unsigned sbase, int sc, int b, int h, int w0,
        const __nv_bfloat16* Wh, const __nv_bfloat16* Wl, int tid) {
    int kk = sc >> 2, q = sc & 3;
    int dy = kk/3 - 1, dx = kk%3 - 1;
    int wc = kk*2 + (q >> 1), wk0 = (q & 1)*32;
    int ci0 = q*32;
    for (int i = tid; i < 1024; i += 256) {
        int buf = i >> 9, idx = i & 511;
        int row = idx >> 2, seg = idx & 3;
        unsigned dst = sbase + buf*ABUF2 + (unsigned)(row*ASTR2 + seg*8)*2;
        cpa16(dst, (buf ? Wl : Wh) + (size_t)wc*8192 + row*64 + wk0 + seg*8, 16);
    }
    int sh = h + dy;
    for (int i = tid; i < 1024; i += 256) {
        int buf = i >> 9, idx = i & 511;
        int p = idx >> 2, seg = idx & 3;
        int sw = w0 + p + dx;
        bool ok = (sw >= 0 && sw < Ww && sh >= 0 && sh < Hh);
        int swc = ok ? sw : 0, shc = ok ? sh : 0;
        unsigned dst = sbase + 2*ABUF2 + buf*ABUF2 + (unsigned)(p*ASTR2 + seg*8)*2;
        cpa16(dst, (buf ? g_xbl : g_xbh) +
              ((size_t)(b*HW) + shc*Ww + swc)*Cc + ci0 + seg*8, ok ? 16 : 0);
    }
    cpcommit();
}
__device__ __forceinline__ void fill_aux32(unsigned sbase, int sc, int b, int h, int w0, int tid) {
    int tap = sc / 5, g = sc - tap*5;
    int dy = tap/3 - 1, dx = tap%3 - 1;
    int wc, wk0;
    if (g < 4) { wc = tap*3 + (g >> 1); wk0 = (g & 1)*32; }
    else       { wc = tap*3 + 2;        wk0 = 0; }
    for (int i = tid; i < 1024; i += 256) {
        int buf = i >> 9, idx = i & 511;
        int row = idx >> 2, seg = idx & 3;
        unsigned dst = sbase + buf*ABUF2 + (unsigned)(row*ASTR2 + seg*8)*2;
        cpa16(dst, (buf ? g_WAl : g_WAh) + (size_t)wc*8192 + row*64 + wk0 + seg*8, 16);
    }
    int sh = h + dy;
    if (g < 4) {
        int ci0 = g*32;
        for (int i = tid; i < 1024; i += 256) {
            int buf = i >> 9, idx = i & 511;
            int p = idx >> 2, seg = idx & 3;
            int sw = w0 + p + dx;
            bool ok = (sw >= 0 && sw < Ww && sh >= 0 && sh < Hh);
            int swc = ok ? sw : 0, shc = ok ? sh : 0;
            unsigned dst = sbase + 2*ABUF2 + buf*ABUF2 + (unsigned)(p*ASTR2 + seg*8)*2;
            cpa16(dst, (buf ? g_xbl : g_xbh) +
                  ((size_t)(b*HW) + shc*Ww + swc)*Cc + ci0 + seg*8, ok ? 16 : 0);
        }
    } else {
        for (int i = tid; i < 1024; i += 256) {
            int buf = i >> 9, idx = i & 511;
            int p = idx >> 2, seg = idx & 3;
            int sw = w0 + p + dx;
            bool ok = (seg < 2) && (sw >= 0 && sw < Ww && sh >= 0 && sh < Hh);
            int swc = (sw >= 0 && sw < Ww) ? sw : 0;
            int shc = (sh >= 0 && sh < Hh) ? sh : 0;
            int sgc = (seg < 2) ? seg : 0;
            unsigned dst = sbase + 2*ABUF2 + buf*ABUF2 + (unsigned)(p*ASTR2 + seg*8)*2;
            cpa16(dst, (buf ? g_atl : g_ath) +
                  ((size_t)(b*HW) + shc*Ww + swc)*16 + sgc*8, ok ? 16 : 0);
        }
    }
    cpcommit();
}

// ---------------- shared MMA step over one K=32 stage --------------------
__device__ __forceinline__ void mma_stage(unsigned sb, int nks, int co0, int pxo,
                                          int r15, int r16, float acc[4][4][4]) {
    unsigned Ah_ = sb, Al_ = sb + ABUF2, Bh_ = sb + 2*ABUF2, Bl_ = sb + 3*ABUF2;
    for (int ks = 0; ks < nks; ks++) {
        unsigned bh[2][4], bl[2][4];
#pragma unroll
        for (int nh = 0; nh < 2; nh++) {
            ldsm4(bh[nh], Bh_ + (unsigned)((pxo + nh*16 + r15)*ASTR2 + ks*16 + r16)*2);
            ldsm4(bl[nh], Bl_ + (unsigned)((pxo + nh*16 + r15)*ASTR2 + ks*16 + r16)*2);
        }
#pragma unroll
        for (int mf = 0; mf < 4; mf++) {
            unsigned ah[4], al[4];
            ldsm4(ah, Ah_ + (unsigned)((co0 + mf*16 + r15)*ASTR2 + ks*16 + r16)*2);
            ldsm4(al, Al_ + (unsigned)((co0 + mf*16 + r15)*ASTR2 + ks*16 + r16)*2);
#pragma unroll
            for (int nf = 0; nf < 4; nf++) {
                int nh = nf >> 1, sel = nf & 1;
                mma16816(acc[mf][nf], ah, bh[nh][sel], bh[nh][sel+2]);
                mma16816(acc[mf][nf], ah, bl[nh][sel], bl[nh][sel+2]);
                mma16816(acc[mf][nf], al, bh[nh][sel], bh[nh][sel+2]);
            }
        }
    }
}

// ---------------- mma.sync base conv, K=32 pipelined ---------------------
__global__ void __launch_bounds__(256) conv_mma(const float* __restrict__ bias) {
    extern __shared__ __align__(16) unsigned char dsm[];
    unsigned s0 = smem_u32(dsm);
    int tid = threadIdx.x;
    int wid = tid >> 5, lane = tid & 31;
    int co0 = (wid & 1)*64, pxo = (wid >> 1)*32;
    int blk = blockIdx.x;
    int b = blk >> 8;
    int px0 = (blk & 255) * 128;
    int h = px0 >> 8, w0 = px0 & 255;
    int r15 = lane & 15, r16 = (lane >> 4)*8;

    float acc[4][4][4];
#pragma unroll
    for (int mf = 0; mf < 4; mf++)
#pragma unroll
        for (int nf = 0; nf < 4; nf++)
#pragma unroll
            for (int q = 0; q < 4; q++) acc[mf][nf][q] = 0.0f;

    fill_conv32(s0, 0, b, h, w0, g_WBh, g_WBl, tid);
    for (int sc = 0; sc < 36; sc++) {
        cpwait0();
        __syncthreads();
        if (sc + 1 < 36)
            fill_conv32(s0 + ((sc+1)&1)*STAGE2, sc+1, b, h, w0, g_WBh, g_WBl, tid);
        mma_stage(s0 + (sc&1)*STAGE2, 2, co0, pxo, r15, r16, acc);
        __syncthreads();
    }
    int gid = lane >> 2, t4 = lane & 3;
#pragma unroll
    for (int mf = 0; mf < 4; mf++) {
#pragma unroll
        for (int nf = 0; nf < 4; nf++) {
            int co = co0 + mf*16 + gid;
            int px = px0 + pxo + nf*8 + t4*2;
            float* d = acc[mf][nf];
            *(float2*)(g_ybase + (size_t)(b*Cc + co  )*HW + px) =
                make_float2(d[0] + bias[co],   d[1] + bias[co]);
            *(float2*)(g_ybase + (size_t)(b*Cc + co+8)*HW + px) =
                make_float2(d[2] + bias[co+8], d[3] + bias[co+8]);
        }
    }
}

// ---------------- mma.sync aux conv, K=32 pipelined ----------------------
__global__ void __launch_bounds__(256) conv_aux_mma(void) {
    extern __shared__ __align__(16) unsigned char dsm[];
    unsigned s0 = smem_u32(dsm);
    int tid = threadIdx.x;
    int wid = tid >> 5, lane = tid & 31;
    int co0 = (wid & 1)*64, pxo = (wid >> 1)*32;
    int blk = blockIdx.x;
    int b = blk >> 8;
    int px0 = (blk & 255) * 128;
    int h = px0 >> 8, w0 = px0 & 255;
    int r15 = lane & 15, r16 = (lane >> 4)*8;

    float acc[4][4][4];
#pragma unroll
    for (int mf = 0; mf < 4; mf++)
#pragma unroll
        for (int nf = 0; nf < 4; nf++)
#pragma unroll
            for (int q = 0; q < 4; q++) acc[mf][nf][q] = 0.0f;

    fill_aux32(s0, 0, b, h, w0, tid);
    for (int sc = 0; sc < 45; sc++) {
        cpwait0();
        __syncthreads();
        if (sc + 1 < 45)
            fill_aux32(s0 + ((sc+1)&1)*STAGE2, sc+1, b, h, w0, tid);
        int g = sc - (sc/5)*5;
        mma_stage(s0 + (sc&1)*STAGE2, (g < 4) ? 2 : 1, co0, pxo, r15, r16, acc);
        __syncthreads();
    }
    int gid = lane >> 2, t4 = lane & 3;
#pragma unroll
    for (int mf = 0; mf < 4; mf++) {
#pragma unroll
        for (int nf = 0; nf < 4; nf++) {
            int px = px0 + pxo + nf*8 + t4*2;
            float* d = acc[mf][nf];
#pragma unroll
            for (int half = 0; half < 2; half++) {
                int co = co0 + mf*16 + gid + half*8;
                float v0 = d[half*2] + g_bF[co], v1 = d[half*2+1] + g_bF[co];
                if (co < 18) {
                    *(float2*)(g_off + (size_t)(b*18 + co)*HW + px) = make_float2(v0, v1);
                } else if (co < 84) {
                    *(float2*)(g_gbuf + (size_t)(b*66 + co - 18)*HW + px) =
                        make_float2(fmaxf(v0, 0.0f), fmaxf(v1, 0.0f));
                }
            }
        }
    }
}

// ---------------- mma.sync deform GEMM + fused gate + blend --------------
__global__ void __launch_bounds__(256) deform_mma(
        const float* __restrict__ defb, const float* __restrict__ gw2,
        const float* __restrict__ gb2, float* __restrict__ out) {
    extern __shared__ __align__(16) unsigned char dsm[];
    __nv_bfloat16* Ah = (__nv_bfloat16*)dsm;
    __nv_bfloat16* Al = Ah + 128*ASTR;
    __nv_bfloat16* Bh = Al + 128*ASTR;
    __nv_bfloat16* Bl = Bh + 128*ASTR;
    __shared__ int   sC[4][128];
    __shared__ float sWt[4][128];
    __shared__ float sGate[128];
    int tid = threadIdx.x;
    int wid = tid >> 5, lane = tid & 31;
    int co0 = (wid & 1)*64, pxo = (wid >> 1)*32;
    int blk = blockIdx.x;
    int b = blk >> 8;
    int px0 = (blk & 255) * 128;
    int r15 = lane & 15, r16 = (lane >> 4)*8;

    if (tid < 128) {
        int pp = px0 + tid;
        float s = gb2[0];
#pragma unroll 6
        for (int c = 0; c < 66; c++)
            s = fmaf(g_gbuf[(size_t)(b*66 + c)*HW + pp], gw2[c], s);
        sGate[tid] = 1.0f / (1.0f + __expf(-s));
    }

    float acc[4][4][4];
#pragma unroll
    for (int mf = 0; mf < 4; mf++)
#pragma unroll
        for (int nf = 0; nf < 4; nf++)
#pragma unroll
            for (int q = 0; q < 4; q++) acc[mf][nf][q] = 0.0f;

    for (int c = 0; c < 18; c++) {
        int kk = c >> 1;
        int ci0 = (c & 1)*64;
        __syncthreads();
        if ((c & 1) == 0 && tid < 128) {
            int pp = px0 + tid;
            int hh = pp >> 8, ww = pp & (Ww-1);
            float fpx = (float)ww + g_off[(size_t)(b*18 + 2*kk    )*HW + pp];
            float fpy = (float)hh + g_off[(size_t)(b*18 + 2*kk + 1)*HW + pp];
            float fx0 = floorf(fpx), fy0 = floorf(fpy);
            int X0 = (int)fx0, Y0 = (int)fy0;
            float fx = fpx - fx0, fy = fpy - fy0;
            float w00 = (1.0f-fx)*(1.0f-fy), w10 = fx*(1.0f-fy);
            float w01 = (1.0f-fx)*fy,        w11 = fx*fy;
            if (X0   < 0 || X0   >= Ww) { w00 = 0.0f; w01 = 0.0f; }
            if (X0+1 < 0 || X0+1 >= Ww) { w10 = 0.0f; w11 = 0.0f; }
            if (Y0   < 0 || Y0   >= Hh) { w00 = 0.0f; w10 = 0.0f; }
            if (Y0+1 < 0 || Y0+1 >= Hh) { w01 = 0.0f; w11 = 0.0f; }
            sC[0][tid] = min(max(X0,   0), Ww-1);
            sC[1][tid] = min(max(X0+1, 0), Ww-1);
            sC[2][tid] = min(max(Y0,   0), Hh-1);
            sC[3][tid] = min(max(Y0+1, 0), Hh-1);
            sWt[0][tid] = w00; sWt[1][tid] = w10; sWt[2][tid] = w01; sWt[3][tid] = w11;
        }
        __syncthreads();
        for (int i = tid; i < 2048; i += 256) {
            int buf = i >> 10, idx = i & 1023;
            int row = idx >> 3, seg = idx & 7;
            *((float4*)((buf ? Al : Ah) + row*ASTR) + seg) =
                *((const float4*)((buf ? g_WDl : g_WDh) + (size_t)c*8192 + row*64) + seg);
        }
        for (int i = tid; i < 2048; i += 256) {
            int p = i >> 4, g = i & 15;
            int cx0 = sC[0][p], cx1 = sC[1][p], cy0 = sC[2][p], cy1 = sC[3][p];
            float w00 = sWt[0][p], w10 = sWt[1][p], w01 = sWt[2][p], w11 = sWt[3][p];
            size_t base = (size_t)(b*HW)*Cc + (size_t)(ci0 + g*4);
            float4 a00 = *(const float4*)(g_xT + base + (size_t)(cy0*Ww + cx0)*Cc);
            float4 a10 = *(const float4*)(g_xT + base + (size_t)(cy0*Ww + cx1)*Cc);
            float4 a01 = *(const float4*)(g_xT + base + (size_t)(cy1*Ww + cx0)*Cc);
            float4 a11 = *(const float4*)(g_xT + base + (size_t)(cy1*Ww + cx1)*Cc);
            float4 r;
            r.x = w00*a00.x + w10*a10.x + w01*a01.x + w11*a11.x;
            r.y = w00*a00.y + w10*a10.y + w01*a01.y + w11*a11.y;
            r.z = w00*a00.z + w10*a10.z + w01*a01.z + w11*a11.z;
            r.w = w00*a00.w + w10*a10.w + w01*a01.w + w11*a11.w;
            __nv_bfloat16 h0, l0, h1, l1, h2, l2, h3, l3;
            bsplit2(r.x, h0, l0); bsplit2(r.y, h1, l1);
            bsplit2(r.z, h2, l2); bsplit2(r.w, h3, l3);
            __nv_bfloat162* dh = (__nv_bfloat162*)(Bh + p*ASTR + g*4);
            dh[0] = __nv_bfloat162(h0, h1); dh[1] = __nv_bfloat162(h2, h3);
            __nv_bfloat162* dl = (__nv_bfloat162*)(Bl + p*ASTR + g*4);
            dl[0] = __nv_bfloat162(l0, l1); dl[1] = __nv_bfloat162(l2, l3);
        }
        __syncthreads();
#pragma unroll
        for (int ks = 0; ks < 4; ks++) {
            unsigned bh[2][4], bl[2][4];
#pragma unroll
            for (int nh = 0; nh < 2; nh++) {
                ldsm4(bh[nh], smem_u32(Bh + (pxo + nh*16 + r15)*ASTR + ks*16 + r16));
                ldsm4(bl[nh], smem_u32(Bl + (pxo + nh*16 + r15)*ASTR + ks*16 + r16));
            }
#pragma unroll
            for (int mf = 0; mf < 4; mf++) {
                unsigned ah[4], al[4];
                ldsm4(ah, smem_u32(Ah + (co0 + mf*16 + r15)*ASTR + ks*16 + r16));
                ldsm4(al, smem_u32(Al + (co0 + mf*16 + r15)*ASTR + ks*16 + r16));
#pragma unroll
                for (int nf = 0; nf < 4; nf++) {
                    int nh = nf >> 1, sel = nf & 1;
                    mma16816(acc[mf][nf], ah, bh[nh][sel], bh[nh][sel+2]);
                    mma16816(acc[mf][nf], ah, bl[nh][sel], bl[nh][sel+2]);
                    mma16816(acc[mf][nf], al, bh[nh][sel], bh[nh][sel+2]);
                }
            }
        }
    }
    int gid = lane >> 2, t4 = lane & 3;
#pragma unroll
    for (int mf = 0; mf < 4; mf++) {
#pragma unroll
        for (int nf = 0; nf < 4; nf++) {
            int co = co0 + mf*16 + gid;
            int pxl = pxo + nf*8 + t4*2;
            int px = px0 + pxl;
            float* d = acc[mf][nf];
            float g0 = sGate[pxl], g1 = sGate[pxl + 1];
            float bs0 = defb[co], bs8 = defb[co+8];
            const float* yb0 = g_ybase + (size_t)(b*Cc + co  )*HW + px;
            const float* yb8 = g_ybase + (size_t)(b*Cc + co+8)*HW + px;
            *(float2*)(out + (size_t)(b*Cc + co  )*HW + px) = make_float2(
                (1.0f-g0)*yb0[0] + g0*(d[0]+bs0), (1.0f-g1)*yb0[1] + g1*(d[1]+bs0));
            *(float2*)(out + (size_t)(b*Cc + co+8)*HW + px) = make_float2(
                (1.0f-g0)*yb8[0] + g0*(d[2]+bs8), (1.0f-g1)*yb8[1] + g1*(d[3]+bs8));
        }
    }
}

// ---------------- host launcher ------------------------------------------
extern "C" void kernel_launch(void* const* d_in, const int* in_sizes, int n_in,
                              void* d_out, int out_size) {
    const float* x      = (const float*)d_in[0];
    const float* off_w  = (const float*)d_in[1];
    const float* off_b  = (const float*)d_in[2];
    const float* gw1    = (const float*)d_in[3];
    const float* gb1    = (const float*)d_in[4];
    const float* gw2    = (const float*)d_in[5];
    const float* gb2    = (const float*)d_in[6];
    const float* base_w = (const float*)d_in[7];
    const float* base_b = (const float*)d_in[8];
    const float* def_w  = (const float*)d_in[9];
    const float* def_b  = (const float*)d_in[10];
    float* out = (float*)d_out;

    const int ONE_SMEM = 4*128*ASTR*2;   // 90112 (deform)
    cudaFuncSetAttribute(conv_mma,     cudaFuncAttributeMaxDynamicSharedMemorySize, PIPE2);
    cudaFuncSetAttribute(conv_aux_mma, cudaFuncAttributeMaxDynamicSharedMemorySize, PIPE2);
    cudaFuncSetAttribute(deform_mma,   cudaFuncAttributeMaxDynamicSharedMemorySize, ONE_SMEM);

    transpose_k<<<dim3(HW/32, Cc/32, Bb), dim3(32, 8)>>>(x);        // 1
    wprep_k<<<(18*8192 + 255)/256, 256>>>(base_w);                  // 2
    wprepD_k<<<(18*8192 + 255)/256, 256>>>(def_w);                  // 3
    conv_mma<<<Bb*256, 256, PIPE2>>>(base_b);                       // 4  <- profiled
    fft_rows_k<<<Bb*Cc*Hh/4, 512>>>(x);                             // 5
    fft_cols_k<<<Bb*KWF*16, 512>>>();                               // 6
    reduce_feh_k<<<Bb*KWF, 128>>>();                                // 7
    resize_fe_k<<<(Bb*HW + 255)/256, 256>>>();                      // 8
    auxtail_k<<<(Bb*HW + 255)/256, 256>>>();                        // 9
    wprepA_k<<<(27*8192 + 255)/256, 256>>>(off_w, off_b, gw1, gb1); // 10
    conv_aux_mma<<<Bb*256, 256, PIPE2>>>();                         // 11
    deform_mma<<<Bb*256, 256, ONE_SMEM>>>(def_b, gw2, gb2, out);    // 12
}